// round 9
// baseline (speedup 1.0000x reference)
#include <cuda_runtime.h>
#include <cuda_bf16.h>
#include <stdint.h>

// Problem constants
#define B_FEAT 128
#define U_UNITS 100000
#define K_NBR 500
#define N_RUNS 10
#define N_PAIRS 124750.0
#define T2 64          // pair tile edge
#define NTP2 36        // 8*9/2 lower-tri tile pairs (incl diagonal)
#define TOTAL_BLOCKS (NTP2 * N_RUNS)
#define YSTRIDE 132    // float row stride: 132 mod 32 == 4 -> conflict-free frags
#define PTHREADS 512

// Scratch (device globals; no allocation allowed)
__device__ float  g_Y[N_RUNS][K_NBR][B_FEAT];   // normalized, tf32-rounded
__device__ float2 g_P[N_RUNS][K_NBR];           // gathered positions
__device__ double g_part[TOTAL_BLOCKS][5];      // per-block partial sums
__device__ int    g_done = 0;                   // finalize counter

struct Choice { int v[N_RUNS]; };

// ---------------------------------------------------------------------------
// Kernel 1: gather + center + normalize + round-to-tf32 (rna) feature cols
// ---------------------------------------------------------------------------
__global__ void prep_kernel(const float* __restrict__ feat,
                            const float* __restrict__ pos,
                            const int*   __restrict__ nbh,
                            Choice ch) {
    int u   = blockIdx.x;
    int run = blockIdx.y;
    int f   = threadIdx.x;
    int wid = f >> 5, lane = f & 31;

    int ind = __ldg(&nbh[ch.v[run] * K_NBR + u]);
    float v = __ldg(&feat[f * U_UNITS + ind]);

    __shared__ float ws[4];
    float s = v;
    #pragma unroll
    for (int o = 16; o > 0; o >>= 1) s += __shfl_xor_sync(0xFFFFFFFFu, s, o);
    if (lane == 0) ws[wid] = s;
    __syncthreads();
    float mean = (ws[0] + ws[1] + ws[2] + ws[3]) * (1.0f / B_FEAT);
    __syncthreads();

    float c = v - mean;
    float q = c * c;
    #pragma unroll
    for (int o = 16; o > 0; o >>= 1) q += __shfl_xor_sync(0xFFFFFFFFu, q, o);
    if (lane == 0) ws[wid] = q;
    __syncthreads();
    float inv = rsqrtf(ws[0] + ws[1] + ws[2] + ws[3]);

    float y = c * inv;
    uint32_t ytf;
    asm("cvt.rna.tf32.f32 %0, %1;" : "=r"(ytf) : "f"(y));
    g_Y[run][u][f] = __uint_as_float(ytf);
    if (f == 0) g_P[run][u] = make_float2(__ldg(&pos[ind * 2]), __ldg(&pos[ind * 2 + 1]));
}

// ---------------------------------------------------------------------------
// Kernel 2: pair sums via tf32 mma.sync.m16n8k8.
// 64x64 tile per block, 512 threads = 16 warps in a 4x4 grid; each warp owns
// a 16x16 D-tile (2 n-blocks). k=128 split into two halves with separate
// accumulators -> 4 independent 8-deep HMMA chains per warp.
// ---------------------------------------------------------------------------
__global__ __launch_bounds__(PTHREADS) void pair_kernel(float* __restrict__ out) {
    extern __shared__ char sraw[];
    float*  Ys = (float*)sraw;                   // Yi [64][132]
    float*  Yt = Ys + T2 * YSTRIDE;              // Yj [64][132]
    float2* Pi = (float2*)(Yt + T2 * YSTRIDE);
    float2* Pj = Pi + T2;

    int run = blockIdx.y;
    int t   = blockIdx.x;
    int ti = 0;
    while ((ti + 1) * (ti + 2) / 2 <= t) ti++;
    int tj = t - ti * (ti + 1) / 2;
    int i0 = ti * T2, j0 = tj * T2;

    int tid = threadIdx.x;

    // stage tiles (row = 132 floats incl padding; write 32 float4)
    for (int idx = tid; idx < T2 * 32; idx += PTHREADS) {
        int r = idx >> 5, c = idx & 31;
        int gi = i0 + r, gj = j0 + r;
        ((float4*)(Ys + r * YSTRIDE))[c] =
            (gi < K_NBR) ? ((const float4*)g_Y[run][gi])[c] : make_float4(0, 0, 0, 0);
        ((float4*)(Yt + r * YSTRIDE))[c] =
            (gj < K_NBR) ? ((const float4*)g_Y[run][gj])[c] : make_float4(0, 0, 0, 0);
    }
    if (tid < T2) {
        Pi[tid] = (i0 + tid < K_NBR) ? g_P[run][i0 + tid] : make_float2(0, 0);
    } else if (tid < 2 * T2) {
        int k = tid - T2;
        Pj[k] = (j0 + k < K_NBR) ? g_P[run][j0 + k] : make_float2(0, 0);
    }
    __syncthreads();

    int lane = tid & 31, w = tid >> 5;
    int wy = w >> 2, wx = w & 3;          // 4x4 warp grid
    int g4 = lane >> 2, q4 = lane & 3;

    const float* Arow0 = Ys + (wy * 16 + g4) * YSTRIDE;       // rows wy*16 + g4 (+8)
    const float* Bbase = Yt + (wx * 16 + g4) * YSTRIDE;       // cols wx*16 + nt*8 + g4

    // acc[half][nt][e]: two k-halves accumulated separately for ILP
    float acc[2][2][4];
    #pragma unroll
    for (int h = 0; h < 2; h++)
        #pragma unroll
        for (int nt = 0; nt < 2; nt++)
            #pragma unroll
            for (int e = 0; e < 4; e++) acc[h][nt][e] = 0.f;

    #pragma unroll
    for (int ks = 0; ks < 8; ks++) {
        #pragma unroll
        for (int h = 0; h < 2; h++) {
            int k0 = (h * 8 + ks) * 8;
            uint32_t a0 = __float_as_uint(Arow0[k0 + q4]);
            uint32_t a1 = __float_as_uint(Arow0[8 * YSTRIDE + k0 + q4]);
            uint32_t a2 = __float_as_uint(Arow0[k0 + q4 + 4]);
            uint32_t a3 = __float_as_uint(Arow0[8 * YSTRIDE + k0 + q4 + 4]);
            #pragma unroll
            for (int nt = 0; nt < 2; nt++) {
                uint32_t b0 = __float_as_uint(Bbase[nt * 8 * YSTRIDE + k0 + q4]);
                uint32_t b1 = __float_as_uint(Bbase[nt * 8 * YSTRIDE + k0 + q4 + 4]);
                asm volatile(
                    "mma.sync.aligned.m16n8k8.row.col.f32.tf32.tf32.f32 "
                    "{%0,%1,%2,%3}, {%4,%5,%6,%7}, {%8,%9}, {%0,%1,%2,%3};"
                    : "+f"(acc[h][nt][0]), "+f"(acc[h][nt][1]),
                      "+f"(acc[h][nt][2]), "+f"(acc[h][nt][3])
                    : "r"(a0), "r"(a1), "r"(a2), "r"(a3), "r"(b0), "r"(b1));
            }
        }
    }

    // epilogue: thread owns D rows {wy*16+g4, +8}, cols {wx*16+nt*8+2*q4, +1}
    float sr = 0.f, sd = 0.f, srd = 0.f, srr = 0.f, sdd = 0.f;
    int r0l = wy * 16 + g4;
    #pragma unroll
    for (int nt = 0; nt < 2; nt++) {
        int c0l = wx * 16 + nt * 8 + 2 * q4;
        #pragma unroll
        for (int e = 0; e < 4; e++) {
            int li = r0l + (e >> 1) * 8;
            int lj = c0l + (e & 1);
            int gi = i0 + li, gj = j0 + lj;
            if (gi < K_NBR && gj < K_NBR && gi > gj) {
                float dot = acc[0][nt][e] + acc[1][nt][e];
                float dx = Pi[li].x - Pj[lj].x;
                float dy = Pi[li].y - Pj[lj].y;
                float ds = 1.0f / (sqrtf(dx * dx + dy * dy) + 1.0f);
                sr  += dot;
                sd  += ds;
                srd += dot * ds;
                srr += dot * dot;
                sdd += ds * ds;
            }
        }
    }

    // block reduce 5 sums
    #pragma unroll
    for (int off = 16; off > 0; off >>= 1) {
        sr  += __shfl_down_sync(0xFFFFFFFFu, sr,  off);
        sd  += __shfl_down_sync(0xFFFFFFFFu, sd,  off);
        srd += __shfl_down_sync(0xFFFFFFFFu, srd, off);
        srr += __shfl_down_sync(0xFFFFFFFFu, srr, off);
        sdd += __shfl_down_sync(0xFFFFFFFFu, sdd, off);
    }
    __shared__ float wsum[16][5];
    if (lane == 0) {
        wsum[w][0] = sr;  wsum[w][1] = sd;  wsum[w][2] = srd;
        wsum[w][3] = srr; wsum[w][4] = sdd;
    }
    __syncthreads();
    if (tid == 0) {
        double a0 = 0, a1 = 0, a2 = 0, a3 = 0, a4 = 0;
        #pragma unroll
        for (int ww = 0; ww < 16; ww++) {
            a0 += wsum[ww][0]; a1 += wsum[ww][1]; a2 += wsum[ww][2];
            a3 += wsum[ww][3]; a4 += wsum[ww][4];
        }
        double* p = g_part[run * NTP2 + t];
        p[0] = a0; p[1] = a1; p[2] = a2; p[3] = a3; p[4] = a4;
    }

    // ---- last-block finalize ----
    __shared__ int isLast;
    if (tid == 0) {
        __threadfence();
        int done = atomicAdd(&g_done, 1);
        isLast = (done == TOTAL_BLOCKS - 1) ? 1 : 0;
    }
    __syncthreads();
    if (!isLast) return;

    __shared__ double red[50];
    if (tid < 50) {
        int rn = tid / 5, cp = tid % 5;
        double s = 0;
        #pragma unroll
        for (int b2 = 0; b2 < NTP2; b2++) s += g_part[rn * NTP2 + b2][cp];
        red[tid] = s;
    }
    __syncthreads();
    __shared__ double lsum[N_RUNS];
    if (tid < N_RUNS) {
        double Sr  = red[tid * 5 + 0], Sd  = red[tid * 5 + 1], Srd = red[tid * 5 + 2];
        double Srr = red[tid * 5 + 3], Sdd = red[tid * 5 + 4];
        double num = Srd - Sr * Sd / N_PAIRS;
        double den = sqrt((Srr - Sr * Sr / N_PAIRS) * (Sdd - Sd * Sd / N_PAIRS));
        lsum[tid] = (1.0 - num / den) * 0.5;
    }
    __syncthreads();
    if (tid == 0) {
        double s = 0;
        #pragma unroll
        for (int i = 0; i < N_RUNS; i++) s += lsum[i];
        out[0] = (float)(s / N_RUNS);
        g_done = 0;  // reset for next graph replay
    }
}

// ---------------------------------------------------------------------------
// Host-side JAX threefry2x32: choice = randint(key(42),(10,),0,100)
// ---------------------------------------------------------------------------
static inline uint32_t rotl32(uint32_t x, int r) { return (x << r) | (x >> (32 - r)); }

static void threefry2x32(uint32_t k0, uint32_t k1, uint32_t c0, uint32_t c1,
                         uint32_t* o0, uint32_t* o1) {
    uint32_t ks0 = k0, ks1 = k1, ks2 = k0 ^ k1 ^ 0x1BD11BDAu;
    uint32_t x0 = c0 + ks0, x1 = c1 + ks1;
    const int rotA[4] = {13, 15, 26, 6};
    const int rotB[4] = {17, 29, 16, 24};
#define TF_ROUND4(R) do { for (int _i = 0; _i < 4; _i++) { \
        x0 += x1; x1 = rotl32(x1, (R)[_i]); x1 ^= x0; } } while (0)
    TF_ROUND4(rotA); x0 += ks1; x1 += ks2 + 1;
    TF_ROUND4(rotB); x0 += ks2; x1 += ks0 + 2;
    TF_ROUND4(rotA); x0 += ks0; x1 += ks1 + 3;
    TF_ROUND4(rotB); x0 += ks1; x1 += ks2 + 4;
    TF_ROUND4(rotA); x0 += ks2; x1 += ks0 + 5;
#undef TF_ROUND4
    *o0 = x0; *o1 = x1;
}

extern "C" void kernel_launch(void* const* d_in, const int* in_sizes, int n_in,
                              void* d_out, int out_size) {
    const float* feat = (const float*)d_in[0];
    const float* pos  = (const float*)d_in[1];
    const int*   nbh  = (const int*)d_in[2];

    uint32_t bits[N_RUNS];
    for (uint32_t i = 0; i < 5; i++) {
        uint32_t o0, o1;
        threefry2x32(0u, 42u, i, i + 5u, &o0, &o1);
        bits[i] = o0;
        bits[i + 5] = o1;
    }
    Choice ch;
    for (int i = 0; i < N_RUNS; i++) {
        uint32_t b = bits[i];
        uint32_t hi = b >> 16, lo = b & 0xFFFFu;
        ch.v[i] = (int)(((hi % 100u) * 96u + (lo % 100u)) % 100u);
    }

    const int SMEM = 2 * T2 * YSTRIDE * (int)sizeof(float) + 2 * T2 * (int)sizeof(float2);
    cudaFuncSetAttribute(pair_kernel, cudaFuncAttributeMaxDynamicSharedMemorySize, SMEM);

    prep_kernel<<<dim3(K_NBR, N_RUNS), B_FEAT>>>(feat, pos, nbh, ch);
    pair_kernel<<<dim3(NTP2, N_RUNS), PTHREADS, SMEM>>>((float*)d_out);
}

// round 10
// speedup vs baseline: 1.7984x; 1.7984x over previous
#include <cuda_runtime.h>
#include <cuda_bf16.h>
#include <stdint.h>

// Problem constants
#define B_FEAT 128
#define U_UNITS 100000
#define K_NBR 500
#define N_RUNS 10
#define N_PAIRS 124750.0
#define T2 32          // pair tile edge
#define NTP2 136       // 16*17/2 lower-tri tile pairs (incl diagonal)
#define TOTAL_BLOCKS (NTP2 * N_RUNS)   // 1360
#define YSTRIDE 132    // float row stride: 132 mod 32 == 4 -> conflict-free frags

// Scratch (device globals; no allocation allowed)
__device__ float  g_Y[N_RUNS][K_NBR][B_FEAT];   // normalized, tf32-rounded
__device__ float2 g_P[N_RUNS][K_NBR];           // gathered positions
__device__ double g_part[TOTAL_BLOCKS][5];      // per-block partial sums
__device__ int    g_done = 0;                   // finalize counter

struct Choice { int v[N_RUNS]; };

// ---------------------------------------------------------------------------
// Kernel 1: gather + center + normalize + round-to-tf32 (rna) feature cols
// ---------------------------------------------------------------------------
__global__ void prep_kernel(const float* __restrict__ feat,
                            const float* __restrict__ pos,
                            const int*   __restrict__ nbh,
                            Choice ch) {
    int u   = blockIdx.x;
    int run = blockIdx.y;
    int f   = threadIdx.x;
    int wid = f >> 5, lane = f & 31;

    int ind = __ldg(&nbh[ch.v[run] * K_NBR + u]);
    float v = __ldg(&feat[f * U_UNITS + ind]);

    __shared__ float ws[4];
    float s = v;
    #pragma unroll
    for (int o = 16; o > 0; o >>= 1) s += __shfl_xor_sync(0xFFFFFFFFu, s, o);
    if (lane == 0) ws[wid] = s;
    __syncthreads();
    float mean = (ws[0] + ws[1] + ws[2] + ws[3]) * (1.0f / B_FEAT);
    __syncthreads();

    float c = v - mean;
    float q = c * c;
    #pragma unroll
    for (int o = 16; o > 0; o >>= 1) q += __shfl_xor_sync(0xFFFFFFFFu, q, o);
    if (lane == 0) ws[wid] = q;
    __syncthreads();
    float inv = rsqrtf(ws[0] + ws[1] + ws[2] + ws[3]);

    float y = c * inv;
    uint32_t ytf;
    asm("cvt.rna.tf32.f32 %0, %1;" : "=r"(ytf) : "f"(y));
    g_Y[run][u][f] = __uint_as_float(ytf);
    if (f == 0) g_P[run][u] = make_float2(__ldg(&pos[ind * 2]), __ldg(&pos[ind * 2 + 1]));
}

// ---------------------------------------------------------------------------
// Kernel 2: pair sums via tf32 mma.sync.m16n8k8.
// 32x32 tile per block, 1360 blocks (high residency: ~34KB smem -> ~6/SM).
// 8 warps in a 2x4 grid; each warp owns one m16n8 D-tile. k=128 split into
// two halves with separate accumulators -> 2 independent 8-deep HMMA chains.
// ---------------------------------------------------------------------------
__global__ __launch_bounds__(256) void pair_kernel(float* __restrict__ out) {
    extern __shared__ char sraw[];
    float*  Ys = (float*)sraw;                   // Yi [32][132]
    float*  Yt = Ys + T2 * YSTRIDE;              // Yj [32][132]
    float2* Pi = (float2*)(Yt + T2 * YSTRIDE);
    float2* Pj = Pi + T2;

    int run = blockIdx.y;
    int t   = blockIdx.x;
    int ti = 0;
    while ((ti + 1) * (ti + 2) / 2 <= t) ti++;
    int tj = t - ti * (ti + 1) / 2;
    int i0 = ti * T2, j0 = tj * T2;

    int tid = threadIdx.x;

    // stage tiles: 32 rows x 32 float4 each
    for (int idx = tid; idx < T2 * 32; idx += 256) {
        int r = idx >> 5, c = idx & 31;
        int gi = i0 + r, gj = j0 + r;
        ((float4*)(Ys + r * YSTRIDE))[c] =
            (gi < K_NBR) ? ((const float4*)g_Y[run][gi])[c] : make_float4(0, 0, 0, 0);
        ((float4*)(Yt + r * YSTRIDE))[c] =
            (gj < K_NBR) ? ((const float4*)g_Y[run][gj])[c] : make_float4(0, 0, 0, 0);
    }
    if (tid < T2) {
        Pi[tid] = (i0 + tid < K_NBR) ? g_P[run][i0 + tid] : make_float2(0, 0);
    } else if (tid < 2 * T2) {
        int k = tid - T2;
        Pj[k] = (j0 + k < K_NBR) ? g_P[run][j0 + k] : make_float2(0, 0);
    }
    __syncthreads();

    int lane = tid & 31, w = tid >> 5;
    int wy = w >> 2, wx = w & 3;          // 2x4 warp grid: rows wy*16, cols wx*8
    int g4 = lane >> 2, q4 = lane & 3;

    const float* Arow0 = Ys + (wy * 16 + g4) * YSTRIDE;   // rows wy*16+g4 (+8)
    const float* Brow  = Yt + (wx * 8 + g4) * YSTRIDE;    // col n = wx*8+g4

    float acc[2][4];
    #pragma unroll
    for (int h = 0; h < 2; h++)
        #pragma unroll
        for (int e = 0; e < 4; e++) acc[h][e] = 0.f;

    #pragma unroll
    for (int ks = 0; ks < 8; ks++) {
        #pragma unroll
        for (int h = 0; h < 2; h++) {
            int k0 = (h * 8 + ks) * 8;
            uint32_t a0 = __float_as_uint(Arow0[k0 + q4]);
            uint32_t a1 = __float_as_uint(Arow0[8 * YSTRIDE + k0 + q4]);
            uint32_t a2 = __float_as_uint(Arow0[k0 + q4 + 4]);
            uint32_t a3 = __float_as_uint(Arow0[8 * YSTRIDE + k0 + q4 + 4]);
            uint32_t b0 = __float_as_uint(Brow[k0 + q4]);
            uint32_t b1 = __float_as_uint(Brow[k0 + q4 + 4]);
            asm volatile(
                "mma.sync.aligned.m16n8k8.row.col.f32.tf32.tf32.f32 "
                "{%0,%1,%2,%3}, {%4,%5,%6,%7}, {%8,%9}, {%0,%1,%2,%3};"
                : "+f"(acc[h][0]), "+f"(acc[h][1]), "+f"(acc[h][2]), "+f"(acc[h][3])
                : "r"(a0), "r"(a1), "r"(a2), "r"(a3), "r"(b0), "r"(b1));
        }
    }

    // epilogue: thread owns D rows {wy*16+g4, +8}, cols {wx*8+2*q4, +1}
    float sr = 0.f, sd = 0.f, srd = 0.f, srr = 0.f, sdd = 0.f;
    int r0l = wy * 16 + g4;
    int c0l = wx * 8 + 2 * q4;
    #pragma unroll
    for (int e = 0; e < 4; e++) {
        int li = r0l + (e >> 1) * 8;
        int lj = c0l + (e & 1);
        int gi = i0 + li, gj = j0 + lj;
        if (gi < K_NBR && gj < K_NBR && gi > gj) {
            float dot = acc[0][e] + acc[1][e];
            float dx = Pi[li].x - Pj[lj].x;
            float dy = Pi[li].y - Pj[lj].y;
            float ds = 1.0f / (sqrtf(dx * dx + dy * dy) + 1.0f);
            sr  += dot;
            sd  += ds;
            srd += dot * ds;
            srr += dot * dot;
            sdd += ds * ds;
        }
    }

    // block reduce 5 sums
    #pragma unroll
    for (int off = 16; off > 0; off >>= 1) {
        sr  += __shfl_down_sync(0xFFFFFFFFu, sr,  off);
        sd  += __shfl_down_sync(0xFFFFFFFFu, sd,  off);
        srd += __shfl_down_sync(0xFFFFFFFFu, srd, off);
        srr += __shfl_down_sync(0xFFFFFFFFu, srr, off);
        sdd += __shfl_down_sync(0xFFFFFFFFu, sdd, off);
    }
    __shared__ float wsum[8][5];
    if (lane == 0) {
        wsum[w][0] = sr;  wsum[w][1] = sd;  wsum[w][2] = srd;
        wsum[w][3] = srr; wsum[w][4] = sdd;
    }
    __syncthreads();
    if (tid == 0) {
        double a0 = 0, a1 = 0, a2 = 0, a3 = 0, a4 = 0;
        #pragma unroll
        for (int ww = 0; ww < 8; ww++) {
            a0 += wsum[ww][0]; a1 += wsum[ww][1]; a2 += wsum[ww][2];
            a3 += wsum[ww][3]; a4 += wsum[ww][4];
        }
        double* p = g_part[run * NTP2 + t];
        p[0] = a0; p[1] = a1; p[2] = a2; p[3] = a3; p[4] = a4;
    }

    // ---- last-block finalize ----
    __shared__ int isLast;
    if (tid == 0) {
        __threadfence();
        int done = atomicAdd(&g_done, 1);
        isLast = (done == TOTAL_BLOCKS - 1) ? 1 : 0;
    }
    __syncthreads();
    if (!isLast) return;

    __shared__ double red[50];
    if (tid < 50) {
        int rn = tid / 5, cp = tid % 5;
        double s = 0;
        for (int b2 = 0; b2 < NTP2; b2++) s += g_part[rn * NTP2 + b2][cp];
        red[tid] = s;
    }
    __syncthreads();
    __shared__ double lsum[N_RUNS];
    if (tid < N_RUNS) {
        double Sr  = red[tid * 5 + 0], Sd  = red[tid * 5 + 1], Srd = red[tid * 5 + 2];
        double Srr = red[tid * 5 + 3], Sdd = red[tid * 5 + 4];
        double num = Srd - Sr * Sd / N_PAIRS;
        double den = sqrt((Srr - Sr * Sr / N_PAIRS) * (Sdd - Sd * Sd / N_PAIRS));
        lsum[tid] = (1.0 - num / den) * 0.5;
    }
    __syncthreads();
    if (tid == 0) {
        double s = 0;
        #pragma unroll
        for (int i = 0; i < N_RUNS; i++) s += lsum[i];
        out[0] = (float)(s / N_RUNS);
        g_done = 0;  // reset for next graph replay
    }
}

// ---------------------------------------------------------------------------
// Host-side JAX threefry2x32: choice = randint(key(42),(10,),0,100)
// ---------------------------------------------------------------------------
static inline uint32_t rotl32(uint32_t x, int r) { return (x << r) | (x >> (32 - r)); }

static void threefry2x32(uint32_t k0, uint32_t k1, uint32_t c0, uint32_t c1,
                         uint32_t* o0, uint32_t* o1) {
    uint32_t ks0 = k0, ks1 = k1, ks2 = k0 ^ k1 ^ 0x1BD11BDAu;
    uint32_t x0 = c0 + ks0, x1 = c1 + ks1;
    const int rotA[4] = {13, 15, 26, 6};
    const int rotB[4] = {17, 29, 16, 24};
#define TF_ROUND4(R) do { for (int _i = 0; _i < 4; _i++) { \
        x0 += x1; x1 = rotl32(x1, (R)[_i]); x1 ^= x0; } } while (0)
    TF_ROUND4(rotA); x0 += ks1; x1 += ks2 + 1;
    TF_ROUND4(rotB); x0 += ks2; x1 += ks0 + 2;
    TF_ROUND4(rotA); x0 += ks0; x1 += ks1 + 3;
    TF_ROUND4(rotB); x0 += ks1; x1 += ks2 + 4;
    TF_ROUND4(rotA); x0 += ks2; x1 += ks0 + 5;
#undef TF_ROUND4
    *o0 = x0; *o1 = x1;
}

extern "C" void kernel_launch(void* const* d_in, const int* in_sizes, int n_in,
                              void* d_out, int out_size) {
    const float* feat = (const float*)d_in[0];
    const float* pos  = (const float*)d_in[1];
    const int*   nbh  = (const int*)d_in[2];

    uint32_t bits[N_RUNS];
    for (uint32_t i = 0; i < 5; i++) {
        uint32_t o0, o1;
        threefry2x32(0u, 42u, i, i + 5u, &o0, &o1);
        bits[i] = o0;
        bits[i + 5] = o1;
    }
    Choice ch;
    for (int i = 0; i < N_RUNS; i++) {
        uint32_t b = bits[i];
        uint32_t hi = b >> 16, lo = b & 0xFFFFu;
        ch.v[i] = (int)(((hi % 100u) * 96u + (lo % 100u)) % 100u);
    }

    const int SMEM = 2 * T2 * YSTRIDE * (int)sizeof(float) + 2 * T2 * (int)sizeof(float2);
    cudaFuncSetAttribute(pair_kernel, cudaFuncAttributeMaxDynamicSharedMemorySize, SMEM);

    prep_kernel<<<dim3(K_NBR, N_RUNS), B_FEAT>>>(feat, pos, nbh, ch);
    pair_kernel<<<dim3(NTP2, N_RUNS), 256, SMEM>>>((float*)d_out);
}